// round 10
// baseline (speedup 1.0000x reference)
#include <cuda_runtime.h>

#define N_COLS    22
#define N_PAIRS   231
#define EMB_NUM   12
#define DIM       64
#define BATCH     4096
#define NFF       (EMB_NUM * EMB_NUM)   // 144
#define ROWS_TILE 32
#define N_TILES   (BATCH / ROWS_TILE)   // 128
#define GRID      148                   // one CTA per SM -> single wave, spin-safe
#define THREADS   512
#define WARPS     16
#define MAIN_ITERS 15                   // ceil(231/16)

// Pair-contribution table: T[p][fi][fj] -> (out0, out1)
__device__ float2   g_T[N_PAIRS * NFF];
__device__ unsigned g_bar;              // monotonic epoch barrier counter

__global__ __launch_bounds__(THREADS) void nasp_fused_kernel(
        const int*   __restrict__ feats,
        const float* __restrict__ tables,
        const float* __restrict__ Ws,    // (231,4,2,64)
        const float* __restrict__ Wc,    // (231,2,128)
        const float* __restrict__ aw,    // (231,5)
        float*       __restrict__ out) {
    __shared__ union {
        struct {                          // phase 1
            float A[8 * DIM];             // a_k * W_small[p][k][o][d], row k*2+o
            float C[4 * DIM];             // a_4 * W_concat[p][o][half], row o*2+half
            float P[EMB_NUM * DIM];       // tables[i][*][:]
            float Q[EMB_NUM * DIM];       // tables[j][*][:]
        } prep;
        struct {                          // phase 2
            int    feat[N_COLS][ROWS_TILE];
            int    ij[N_PAIRS + 1];
            float2 part[WARPS][ROWS_TILE];
        } mn;
    } sm;

    int tid  = threadIdx.x;
    int warp = tid >> 5, lane = tid & 31;

    // ---------------- Phase 1: build g_T (pairs strided over CTAs) ----------
    for (int p = blockIdx.x; p < N_PAIRS; p += GRID) {
        // triu_indices(22, k=1) row-major unrank
        int i = 0, rem = p, span = N_COLS - 1;
        while (rem >= span) { rem -= span; i++; span--; }
        int j = i + 1 + rem;

        // Stage weights with arch_weights folded in (512 threads, exact fit)
        sm.prep.A[tid] = Ws[p * 512 + tid] * aw[p * 5 + (tid >> 7)];
        if (tid < 256) sm.prep.C[tid] = Wc[p * 256 + tid] * aw[p * 5 + 4];
        for (int idx = tid; idx < EMB_NUM * DIM; idx += THREADS) {
            sm.prep.P[idx] = tables[(i * EMB_NUM) * DIM + idx];
            sm.prep.Q[idx] = tables[(j * EMB_NUM) * DIM + idx];
        }
        __syncthreads();

        for (int c = warp; c < NFF; c += WARPS) {
            int fi = c / EMB_NUM;
            int fj = c - fi * EMB_NUM;
            float acc0 = 0.f, acc1 = 0.f;
#pragma unroll
            for (int r = 0; r < 2; r++) {
                int d = lane + 32 * r;
                float P = sm.prep.P[fi * DIM + d], Q = sm.prep.Q[fj * DIM + d];
                float s   = P + Q;
                float m   = P * Q;
                float mx  = fmaxf(P, Q);
                float mnv = fminf(P, Q);
                acc0 += s * sm.prep.A[0 * DIM + d] + m   * sm.prep.A[2 * DIM + d]
                      + mx * sm.prep.A[4 * DIM + d] + mnv * sm.prep.A[6 * DIM + d]
                      + P * sm.prep.C[0 * DIM + d] + Q * sm.prep.C[1 * DIM + d];
                acc1 += s * sm.prep.A[1 * DIM + d] + m   * sm.prep.A[3 * DIM + d]
                      + mx * sm.prep.A[5 * DIM + d] + mnv * sm.prep.A[7 * DIM + d]
                      + P * sm.prep.C[2 * DIM + d] + Q * sm.prep.C[3 * DIM + d];
            }
#pragma unroll
            for (int off = 16; off; off >>= 1) {
                acc0 += __shfl_xor_sync(0xffffffffu, acc0, off);
                acc1 += __shfl_xor_sync(0xffffffffu, acc1, off);
            }
            if (lane == 0) g_T[p * NFF + c] = make_float2(acc0, acc1);
        }
        __syncthreads();   // protect smem before restaging next pair
    }
    __syncthreads();       // close prep-union use before mn staging

    // ------- Overlap: stage phase-2 inputs (independent of g_T) -------------
    int tile = blockIdx.x;
    int base = tile * ROWS_TILE;
    if (tile < N_TILES) {
        for (int idx = tid; idx < ROWS_TILE * N_COLS; idx += THREADS) {
            int r = idx / N_COLS, c = idx - r * N_COLS;
            sm.mn.feat[c][r] = feats[(base + r) * N_COLS + c];
        }
        if (tid <= N_PAIRS) {                    // unrank all pairs locally
            int p = tid;
            int i = 0, rem = p, span = N_COLS - 1;
            while (rem >= span) { rem -= span; i++; span--; }
            sm.mn.ij[tid] = (i << 5) | (i + 1 + rem); // tid==231 -> dummy
        }
    }
    __syncthreads();

    // -------- Grid barrier (monotonic epoch, replay-safe, busy-wait) --------
    // NO __nanosleep: measured on GB300 it sleeps ~0.9ms regardless of the
    // requested 64ns, turning a <1us barrier into a 900us kernel (R7 data).
    if (tid == 0) {
        __threadfence();                          // release: publish g_T
        unsigned old    = atomicAdd(&g_bar, 1u);
        unsigned target = (old / GRID + 1u) * GRID;
        while (*(volatile unsigned*)&g_bar < target) { /* ~250cyc L2 poll */ }
        __threadfence();                          // acquire: order g_T reads
    }
    __syncthreads();

    // ---------------- Phase 2: batch gather (tiles 0..127 on CTAs 0..127) ---
    if (tile >= N_TILES) return;

    float a0 = 0.f, a1 = 0.f;
#pragma unroll
    for (int t = 0; t < MAIN_ITERS; t++) {
        int p = warp + WARPS * t;
        if (p < N_PAIRS) {
            int ij = sm.mn.ij[p];                // uniform -> smem broadcast
            int fi = sm.mn.feat[ij >> 5][lane];  // conflict-free LDS
            int fj = sm.mn.feat[ij & 31][lane];
            float2 v = __ldg(&g_T[p * NFF + fi * EMB_NUM + fj]);
            a0 += v.x;
            a1 += v.y;
        }
    }
    sm.mn.part[warp][lane] = make_float2(a0, a1);
    __syncthreads();

    if (tid < ROWS_TILE * 2) {
        int r = tid >> 1, o = tid & 1;
        float s = 0.f;
#pragma unroll
        for (int ww = 0; ww < WARPS; ww++)
            s += o ? sm.mn.part[ww][r].y : sm.mn.part[ww][r].x;
        out[(base + r) * 2 + o] = s;
    }
}

extern "C" void kernel_launch(void* const* d_in, const int* in_sizes, int n_in,
                              void* d_out, int out_size) {
    const int*   feats  = (const int*)  d_in[0];
    const float* tables = (const float*)d_in[1];
    const float* Ws     = (const float*)d_in[2];
    const float* Wc     = (const float*)d_in[3];
    const float* aw     = (const float*)d_in[4];
    float* out = (float*)d_out;

    nasp_fused_kernel<<<GRID, THREADS>>>(feats, tables, Ws, Wc, aw, out);
}

// round 17
// speedup vs baseline: 1.0363x; 1.0363x over previous
#include <cuda_runtime.h>

#define N_COLS    22
#define N_PAIRS   231
#define EMB_NUM   12
#define DIM       64
#define BATCH     4096
#define NFF       (EMB_NUM * EMB_NUM)   // 144
#define ROWS_TILE 32
#define MAIN_WARPS 16
#define MAIN_ITERS 15                   // ceil(231/16)
#define PREP_THREADS 512
#define PREP_WARPS   16

// Precomputed pair-contribution table: T[p][fi][fj] -> (out0, out1)
__device__ float2 g_T[N_PAIRS * NFF];

// One CTA per pair, 16 warps. Stage alpha-folded weights + candidate table
// rows in smem, then warps sweep the 144 (fi,fj) combos (9 each).
__global__ __launch_bounds__(PREP_THREADS) void nasp_prep_kernel(
        const float* __restrict__ tables,
        const float* __restrict__ Ws,   // (231,4,2,64)
        const float* __restrict__ Wc,   // (231,2,128)
        const float* __restrict__ aw) { // (231,5)
    __shared__ float sA[8 * DIM];       // a_k * W_small[p][k][o][d], row k*2+o
    __shared__ float sC[4 * DIM];       // a_4 * W_concat[p][o][half], row o*2+half
    __shared__ float sP[EMB_NUM * DIM]; // tables[i][*][:]
    __shared__ float sQ[EMB_NUM * DIM]; // tables[j][*][:]

    // PDL: allow the dependent (main) kernel to begin launching now; it will
    // block in cudaGridDependencySynchronize() until this grid completes.
    cudaTriggerProgrammaticLaunchCompletion();

    int p   = blockIdx.x;
    int tid = threadIdx.x;

    // triu_indices(22, k=1) row-major unrank
    int i = 0, rem = p, span = N_COLS - 1;
    while (rem >= span) { rem -= span; i++; span--; }
    int j = i + 1 + rem;

    // Stage weights with arch_weights folded in (512 threads: exact fits)
    sA[tid] = Ws[p * 512 + tid] * aw[p * 5 + (tid >> 7)];
    if (tid < 256) sC[tid] = Wc[p * 256 + tid] * aw[p * 5 + 4];
    for (int idx = tid; idx < EMB_NUM * DIM; idx += PREP_THREADS) {
        sP[idx] = tables[(i * EMB_NUM) * DIM + idx];
        sQ[idx] = tables[(j * EMB_NUM) * DIM + idx];
    }
    __syncthreads();

    int warp = tid >> 5, lane = tid & 31;
    for (int c = warp; c < NFF; c += PREP_WARPS) {
        int fi = c / EMB_NUM;
        int fj = c - fi * EMB_NUM;
        float acc0 = 0.f, acc1 = 0.f;
#pragma unroll
        for (int r = 0; r < 2; r++) {
            int d = lane + 32 * r;
            float P = sP[fi * DIM + d], Q = sQ[fj * DIM + d];
            float s   = P + Q;
            float m   = P * Q;
            float mx  = fmaxf(P, Q);
            float mnv = fminf(P, Q);
            acc0 += s * sA[0 * DIM + d] + m   * sA[2 * DIM + d]
                  + mx * sA[4 * DIM + d] + mnv * sA[6 * DIM + d]
                  + P * sC[0 * DIM + d] + Q * sC[1 * DIM + d];
            acc1 += s * sA[1 * DIM + d] + m   * sA[3 * DIM + d]
                  + mx * sA[5 * DIM + d] + mnv * sA[7 * DIM + d]
                  + P * sC[2 * DIM + d] + Q * sC[3 * DIM + d];
        }
#pragma unroll
        for (int off = 16; off; off >>= 1) {
            acc0 += __shfl_xor_sync(0xffffffffu, acc0, off);
            acc1 += __shfl_xor_sync(0xffffffffu, acc1, off);
        }
        if (lane == 0) g_T[p * NFF + c] = make_float2(acc0, acc1);
    }
}

// CTA = 32-row tile, 16 warps. Lane = row, warp = pair-subset.
// Under PDL the prologue (feat staging, unranking) overlaps prep, and
// cudaGridDependencySynchronize() gates the g_T reads. Under a plain launch
// the sync is trivially satisfied (stream order) — same binary is correct.
__global__ __launch_bounds__(512) void nasp_main_kernel(
        const int* __restrict__ feats,
        float* __restrict__ out) {
    __shared__ int    s_feat[N_COLS][ROWS_TILE];     // transposed feat tile
    __shared__ int    s_ij[N_PAIRS + 1];
    __shared__ float2 s_part[MAIN_WARPS][ROWS_TILE]; // per-warp partials

    int tid  = threadIdx.x;
    int base = blockIdx.x * ROWS_TILE;

    for (int idx = tid; idx < ROWS_TILE * N_COLS; idx += 512) {
        int r = idx / N_COLS, c = idx - r * N_COLS;
        s_feat[c][r] = feats[(base + r) * N_COLS + c];
    }
    if (tid <= N_PAIRS) {                       // unrank pair indices locally
        int p = tid;
        int i = 0, rem = p, span = N_COLS - 1;
        while (rem >= span) { rem -= span; i++; span--; }
        s_ij[tid] = (i << 5) | (i + 1 + rem);   // tid==231 -> harmless dummy
    }

    // Wait for prep grid completion (memory-visibility inclusive).
    cudaGridDependencySynchronize();
    __syncthreads();

    int w = tid >> 5, l = tid & 31;   // l = row within tile
    float a0 = 0.f, a1 = 0.f;
#pragma unroll
    for (int t = 0; t < MAIN_ITERS; t++) {
        int p = w + MAIN_WARPS * t;
        if (p < N_PAIRS) {
            int ij = s_ij[p];                 // uniform across warp -> broadcast
            int fi = s_feat[ij >> 5][l];      // conflict-free LDS
            int fj = s_feat[ij & 31][l];
            float2 v = __ldg(&g_T[p * NFF + fi * EMB_NUM + fj]);
            a0 += v.x;
            a1 += v.y;
        }
    }
    s_part[w][l] = make_float2(a0, a1);
    __syncthreads();

    // 64 threads: thread t -> (row, out-component)
    if (tid < ROWS_TILE * 2) {
        int r = tid >> 1, o = tid & 1;
        float s = 0.f;
#pragma unroll
        for (int ww = 0; ww < MAIN_WARPS; ww++)
            s += o ? s_part[ww][r].y : s_part[ww][r].x;
        out[(base + r) * 2 + o] = s;
    }
}

extern "C" void kernel_launch(void* const* d_in, const int* in_sizes, int n_in,
                              void* d_out, int out_size) {
    const int*   feats  = (const int*)  d_in[0];
    const float* tables = (const float*)d_in[1];
    const float* Ws     = (const float*)d_in[2];
    const float* Wc     = (const float*)d_in[3];
    const float* aw     = (const float*)d_in[4];
    float* out = (float*)d_out;

    nasp_prep_kernel<<<N_PAIRS, PREP_THREADS>>>(tables, Ws, Wc, aw);

    // Try PDL (Programmatic Stream Serialization): main may begin while prep
    // runs; cudaGridDependencySynchronize() inside gates the g_T reads.
    cudaLaunchConfig_t cfg = {};
    cfg.gridDim  = dim3(BATCH / ROWS_TILE, 1, 1);
    cfg.blockDim = dim3(512, 1, 1);
    cfg.dynamicSmemBytes = 0;
    cudaLaunchAttribute attrs[1];
    attrs[0].id = cudaLaunchAttributeProgrammaticStreamSerialization;
    attrs[0].val.programmaticStreamSerializationAllowed = 1;
    cfg.attrs    = attrs;
    cfg.numAttrs = 1;
    cudaError_t err = cudaLaunchKernelEx(&cfg, nasp_main_kernel, feats, out);
    if (err != cudaSuccess) {
        // PDL unsupported here (e.g. rejected under graph capture):
        // plain launch is functionally identical (stream order replaces PDL).
        cudaGetLastError();   // clear sticky error
        nasp_main_kernel<<<BATCH / ROWS_TILE, 512>>>(feats, out);
    }
}